// round 6
// baseline (speedup 1.0000x reference)
#include <cuda_runtime.h>
#include <cuda_bf16.h>
#include <cuda_fp16.h>
#include <cuda_fp8.h>
#include <cstdint>
#include <cfloat>
#include <math.h>

#define B_  16
#define D_  256
#define T_  4096
#define N_  65536                  // B_*T_
#define K_  1024
#define Z_  16777216               // N_*D_

#define CH      32                 // codewords per chunk
#define NCHUNK  (K_/CH)            // 32
#define LDQ     272                // padded smem row stride in BYTES (17 x 16B, odd -> conflict-free ldmatrix)
#define CMAX    24                 // candidate list capacity per row
#define MARGIN  12.0f              // ~7.5 sigma of fp8 score noise

// ---------------- scratch (static device memory) ----------------
__device__ __align__(16) float   g_Xf[N_ * D_];            // 64MB fp32 transposed inputs [n][d]
__device__ __align__(16) uint8_t g_Xq[N_ * D_];            // 16MB e4m3 transposed inputs
__device__ __align__(16) uint8_t g_Eq[K_ * D_];            // 256KB e4m3 codebook
__device__ __align__(16) float g_e2[K_];
__device__ int   g_qidx[N_];
__device__ float g_qd2[N_];
__device__ int   g_counts[K_];

// ---------------- helpers ----------------
__device__ __forceinline__ unsigned fkey(float f) {        // order-preserving float->uint
    unsigned u = __float_as_uint(f);
    return u ^ ((unsigned)((int)u >> 31) | 0x80000000u);
}
__device__ __forceinline__ float fdecode(unsigned u) {
    unsigned m = (u >> 31) ? 0x80000000u : 0xFFFFFFFFu;
    return __uint_as_float(u ^ m);
}
// pack two floats -> e4m3x2 (lo in low byte)
__device__ __forceinline__ unsigned short pk8(float lo, float hi) {
    unsigned short r;
    asm("cvt.rn.satfinite.e4m3x2.f32 %0, %1, %2;" : "=h"(r) : "f"(hi), "f"(lo));
    return r;
}
__device__ __forceinline__ uint32_t pk8x4(float4 v) {
    return (uint32_t)pk8(v.x, v.y) | ((uint32_t)pk8(v.z, v.w) << 16);
}
__device__ __forceinline__ void cp16(uint32_t dst, const void* src) {
    asm volatile("cp.async.cg.shared.global [%0], [%1], 16;" :: "r"(dst), "l"(src));
}
__device__ __forceinline__ void ldsm4(uint32_t r[4], uint32_t addr) {
    asm volatile("ldmatrix.sync.aligned.m8n8.x4.shared.b16 {%0,%1,%2,%3}, [%4];"
                 : "=r"(r[0]), "=r"(r[1]), "=r"(r[2]), "=r"(r[3]) : "r"(addr));
}
// fp8 e4m3 mma, k=32 (fragments produced by the b16-view ldmatrix above)
__device__ __forceinline__ void mma16832(float c[4], const uint32_t a[4],
                                         uint32_t b0, uint32_t b1) {
    asm volatile(
        "mma.sync.aligned.m16n8k32.row.col.f32.e4m3.e4m3.f32 "
        "{%0,%1,%2,%3}, {%4,%5,%6,%7}, {%8,%9}, {%0,%1,%2,%3};"
        : "+f"(c[0]), "+f"(c[1]), "+f"(c[2]), "+f"(c[3])
        : "r"(a[0]), "r"(a[1]), "r"(a[2]), "r"(a[3]), "r"(b0), "r"(b1));
}
// exact fp32 distance, warp-cooperative
__device__ __forceinline__ float dist2(float4 xv0, float4 xv1, const float* e, int lane) {
    const float4* er = (const float4*)e;
    float4 ev0 = er[lane * 2], ev1 = er[lane * 2 + 1];
    float d0 = xv0.x - ev0.x, d1 = xv0.y - ev0.y, d2 = xv0.z - ev0.z, d3 = xv0.w - ev0.w;
    float part = d0 * d0 + d1 * d1 + d2 * d2 + d3 * d3;
    d0 = xv1.x - ev1.x; d1 = xv1.y - ev1.y; d2 = xv1.z - ev1.z; d3 = xv1.w - ev1.w;
    part += d0 * d0 + d1 * d1 + d2 * d2 + d3 * d3;
    #pragma unroll
    for (int off = 16; off; off >>= 1) part += __shfl_xor_sync(0xffffffffu, part, off);
    return part;
}

// ---------------- prep: counts=0, e4m3 codebook, e2 ----------------
__global__ void k_prep(const float* __restrict__ embed) {
    __shared__ float wsum[8];
    int tid = threadIdx.x;
    int i = blockIdx.x * 256 + tid;                  // float4 index over K_*D_/4 = 65536
    float4 v = ((const float4*)embed)[i];
    ((uint32_t*)g_Eq)[i] = pk8x4(v);
    float s = v.x * v.x + v.y * v.y + v.z * v.z + v.w * v.w;
    #pragma unroll
    for (int off = 16; off; off >>= 1) s += __shfl_xor_sync(0xffffffffu, s, off);
    if ((tid & 31) == 0) wsum[tid >> 5] = s;
    if (blockIdx.x < 4) g_counts[blockIdx.x * 256 + tid] = 0;
    __syncthreads();
    if (tid < 4) g_e2[blockIdx.x * 4 + tid] = wsum[2 * tid] + wsum[2 * tid + 1];
}

// inputs (B, D, T) -> g_Xf fp32 [n][d] + g_Xq e4m3 [n][d]
__global__ void k_transpose(const float* __restrict__ in) {
    __shared__ float tile[32][33];
    int b = blockIdx.z, d0 = blockIdx.y * 32, t0 = blockIdx.x * 32;
    int tx = threadIdx.x, ty = threadIdx.y;
    const float* src = in + ((size_t)b * D_ + d0) * T_ + t0;
    #pragma unroll
    for (int i = 0; i < 4; i++) tile[ty + 8 * i][tx] = src[(size_t)(ty + 8 * i) * T_ + tx];
    __syncthreads();
    float* dst = g_Xf + ((size_t)b * T_ + t0) * D_ + d0;
    #pragma unroll
    for (int i = 0; i < 4; i++) dst[(size_t)(ty + 8 * i) * D_ + tx] = tile[tx][ty + 8 * i];
    if (tx < 8) {
        #pragma unroll
        for (int i = 0; i < 4; i++) {
            int t = ty + 8 * i;
            float4 q = make_float4(tile[4 * tx][t], tile[4 * tx + 1][t],
                                   tile[4 * tx + 2][t], tile[4 * tx + 3][t]);
            *reinterpret_cast<uint32_t*>(g_Xq + ((size_t)(b * T_ + t0 + t)) * D_ + d0 + 4 * tx)
                = pk8x4(q);
        }
    }
}

// ---------------- main: fp8 mma scores + online candidates + exact refine ----------------
__global__ void __launch_bounds__(256, 3) k_main(const float* __restrict__ embed) {
    extern __shared__ char sm[];
    char* Xs = sm;                                                 // 128 x LDQ   (34816)
    char* Es = sm + 128 * LDQ;                                     // 2 x 32 x LDQ (17408)
    float*    e2s     = (float*)(sm + 128 * LDQ + 2 * CH * LDQ);   // 1024 floats
    unsigned* rowminU = (unsigned*)(e2s + K_);                     // 128
    int*      cnt     = (int*)(rowminU + 128);                     // 128
    unsigned* list    = (unsigned*)(cnt + 128);                    // 128*CMAX

    const int tid  = threadIdx.x;
    const int Nbase = blockIdx.x * 128;
    const int lane = tid & 31, w = tid >> 5;
    const int wm = w & 3, wn = w >> 2;
    const int g = lane >> 2, tg = lane & 3;

    const uint32_t XsA  = (uint32_t)__cvta_generic_to_shared(Xs);
    const uint32_t EsA0 = (uint32_t)__cvta_generic_to_shared(Es);
    const uint32_t EsA1 = EsA0 + CH * LDQ;

    // ---- prologue: group A = X tile + E0 ; group B = E1 ----
    {
        const uint8_t* src = g_Xq + (size_t)Nbase * D_;
        #pragma unroll
        for (int i = 0; i < 8; i++) {
            int j = tid + i * 256, row = j >> 4, u = j & 15;
            cp16(XsA + row * LDQ + u * 16, src + (size_t)row * D_ + u * 16);
        }
        const uint8_t* es = g_Eq;
        #pragma unroll
        for (int i = 0; i < 2; i++) {
            int j = tid + i * 256, row = j >> 4, u = j & 15;
            cp16(EsA0 + row * LDQ + u * 16, es + (size_t)row * D_ + u * 16);
        }
        asm volatile("cp.async.commit_group;");
        es = g_Eq + CH * D_;
        #pragma unroll
        for (int i = 0; i < 2; i++) {
            int j = tid + i * 256, row = j >> 4, u = j & 15;
            cp16(EsA1 + row * LDQ + u * 16, es + (size_t)row * D_ + u * 16);
        }
        asm volatile("cp.async.commit_group;");
    }
    // e2 table + per-row state init (overlaps cp.async)
    ((float4*)e2s)[tid] = ((const float4*)g_e2)[tid];
    if (tid < 128) { rowminU[tid] = 0xFFFFFFFFu; cnt[tid] = 0; }

    const uint32_t aAddr = XsA + (uint32_t)((wm * 32 + (lane & 15)) * LDQ + (lane >> 4) * 16);
    const uint32_t bOff  = (uint32_t)((wn * 16 + (lane & 15)) * LDQ + (lane >> 4) * 16);

    #pragma unroll 1
    for (int c = 0; c < NCHUNK; c++) {
        if (c == 0) { asm volatile("cp.async.wait_group 1;" ::: "memory"); }
        else        { asm volatile("cp.async.wait_group 0;" ::: "memory"); }
        __syncthreads();   // buffer (c+1)&1 free (last read in chunk c-1) + chunk c's E landed

        // prefetch chunk c+1 into its buffer (full chunk of time to land)
        if (c >= 1 && c + 1 < NCHUNK) {
            uint32_t dstA = ((c + 1) & 1) ? EsA1 : EsA0;
            const uint8_t* es = g_Eq + (size_t)(c + 1) * CH * D_;
            #pragma unroll
            for (int i = 0; i < 2; i++) {
                int j = tid + i * 256, row = j >> 4, u = j & 15;
                cp16(dstA + row * LDQ + u * 16, es + (size_t)row * D_ + u * 16);
            }
            asm volatile("cp.async.commit_group;");
        }

        const uint32_t bAddr = ((c & 1) ? EsA1 : EsA0) + bOff;

        float acc[2][2][4];
        #pragma unroll
        for (int tm = 0; tm < 2; tm++)
            #pragma unroll
            for (int tn = 0; tn < 2; tn++)
                #pragma unroll
                for (int q = 0; q < 4; q++) acc[tm][tn][q] = 0.f;

        #pragma unroll
        for (int ks = 0; ks < 8; ks++) {               // k32 per step: 8 steps cover D=256
            uint32_t a0[4], a1[4], b0[4];
            ldsm4(a0, aAddr + ks * 32);
            ldsm4(a1, aAddr + 16 * LDQ + ks * 32);
            ldsm4(b0, bAddr + ks * 32);
            mma16832(acc[0][0], a0, b0[0], b0[2]);
            mma16832(acc[0][1], a0, b0[1], b0[3]);
            mma16832(acc[1][0], a1, b0[0], b0[2]);
            mma16832(acc[1][1], a1, b0[1], b0[3]);
        }

        // scores + running row-min
        float lmin[4] = {FLT_MAX, FLT_MAX, FLT_MAX, FLT_MAX};
        #pragma unroll
        for (int tm = 0; tm < 2; tm++) {
            #pragma unroll
            for (int tn = 0; tn < 2; tn++) {
                int kc = c * CH + wn * 16 + tn * 8 + tg * 2;
                float e20 = e2s[kc], e21 = e2s[kc + 1];
                acc[tm][tn][0] = fmaf(-2.f, acc[tm][tn][0], e20);
                acc[tm][tn][1] = fmaf(-2.f, acc[tm][tn][1], e21);
                acc[tm][tn][2] = fmaf(-2.f, acc[tm][tn][2], e20);
                acc[tm][tn][3] = fmaf(-2.f, acc[tm][tn][3], e21);
                lmin[tm * 2 + 0] = fminf(lmin[tm * 2 + 0], fminf(acc[tm][tn][0], acc[tm][tn][1]));
                lmin[tm * 2 + 1] = fminf(lmin[tm * 2 + 1], fminf(acc[tm][tn][2], acc[tm][tn][3]));
            }
        }
        #pragma unroll
        for (int s = 0; s < 4; s++) {
            float v = lmin[s];
            v = fminf(v, __shfl_xor_sync(0xffffffffu, v, 1));
            v = fminf(v, __shfl_xor_sync(0xffffffffu, v, 2));
            if (tg == 0) {
                int row = wm * 32 + (s >> 1) * 16 + (s & 1) * 8 + g;
                atomicMin(&rowminU[row], fkey(v));
            }
        }
        // chunk 0 needs a converged min; stale mins are provably safe afterwards
        if (c == 0) __syncthreads();

        // candidate collection vs current (possibly stale) row minima + MARGIN
        float thr[4];
        #pragma unroll
        for (int s = 0; s < 4; s++) {
            int row = wm * 32 + (s >> 1) * 16 + (s & 1) * 8 + g;
            thr[s] = fdecode(rowminU[row]) + MARGIN;
        }
        #pragma unroll
        for (int tm = 0; tm < 2; tm++)
            #pragma unroll
            for (int tn = 0; tn < 2; tn++)
                #pragma unroll
                for (int q = 0; q < 4; q++) {
                    float sc = acc[tm][tn][q];
                    int slot = tm * 2 + (q >> 1);
                    if (sc <= thr[slot]) {
                        int row = wm * 32 + tm * 16 + (q >> 1) * 8 + g;
                        int kk  = c * CH + wn * 16 + tn * 8 + tg * 2 + (q & 1);
                        int pos = atomicAdd(&cnt[row], 1);
                        if (pos < CMAX)
                            list[row * CMAX + pos] =
                                ((unsigned)kk << 16) |
                                (unsigned)__half_as_ushort(__float2half_rn(sc));
                    }
                }
    }
    __syncthreads();

    // ---- exact refine: warp w owns rows [w*16, w*16+16) ----
    for (int rr = 0; rr < 16; rr++) {
        int row = w * 16 + rr;
        size_t n = (size_t)Nbase + row;
        float rmn = fdecode(rowminU[row]);
        int c_ = cnt[row];
        const float4* xr = (const float4*)(g_Xf + n * D_);
        float4 xv0 = xr[lane * 2], xv1 = xr[lane * 2 + 1];
        float bestd = FLT_MAX; int bestk = 0;
        if (c_ <= CMAX) {
            float thr = rmn + MARGIN + 1.0f;   // + half-precision storage slack
            unsigned e = (lane < c_) ? list[row * CMAX + lane] : 0u;
            float sh = (lane < c_)
                ? __half2float(__ushort_as_half((unsigned short)(e & 0xFFFFu))) : FLT_MAX;
            unsigned mk = __ballot_sync(0xffffffffu, sh <= thr);
            while (mk) {
                int j = __ffs(mk) - 1; mk &= mk - 1;
                int kc = (int)(__shfl_sync(0xffffffffu, e, j) >> 16);
                float part = dist2(xv0, xv1, embed + (size_t)kc * D_, lane);
                if (part < bestd || (part == bestd && kc < bestk)) { bestd = part; bestk = kc; }
            }
        } else {
            // overflow fallback (rare): exact scan of all codewords
            for (int kc = 0; kc < K_; kc++) {
                float part = dist2(xv0, xv1, embed + (size_t)kc * D_, lane);
                if (part < bestd) { bestd = part; bestk = kc; }
            }
        }
        if (lane == 0) {
            g_qidx[n] = bestk;
            g_qd2[n]  = bestd;
            atomicAdd(&g_counts[bestk], 1);
        }
    }
}

// ---------------- z_q gather back to (B, D, T): warp owns 32-d slice of 32 t ----------------
__global__ void __launch_bounds__(256) k_gather(const float* __restrict__ embed,
                                                float* __restrict__ out, int out_size) {
    if (out_size < Z_) return;
    int lane = threadIdx.x & 31, w = threadIdx.x >> 5;
    int n0 = blockIdx.x * 32;
    int b  = n0 >> 12;
    int t  = (n0 & (T_ - 1)) + lane;
    int kt = g_qidx[n0 + lane];
    const float4* er = (const float4*)(embed + (size_t)kt * D_) + w * 8;
    float* ob = out + (size_t)b * D_ * T_ + (size_t)(w * 32) * T_ + t;
    #pragma unroll
    for (int q = 0; q < 8; q++) {
        float4 v = er[q];
        ob[(size_t)(q * 4) * T_]       = v.x;
        ob[(size_t)(q * 4 + 1) * T_]   = v.y;
        ob[(size_t)(q * 4 + 2) * T_]   = v.z;
        ob[(size_t)(q * 4 + 3) * T_]   = v.w;
    }
}

// ---------------- scalars: loss, kldiv (constant), perplexity ----------------
__global__ void k_final(float* __restrict__ out, int out_size) {
    __shared__ float sh[1024], sd[1024];
    int tid = threadIdx.x;
    float p = (float)g_counts[tid] * (1.0f / 65536.0f);
    sh[tid] = -p * logf(p + 1e-10f);
    float ds = 0.f;
    #pragma unroll 8
    for (int i = 0; i < 64; i++) ds += g_qd2[tid + i * 1024];
    sd[tid] = ds;
    __syncthreads();
    for (int s = 512; s; s >>= 1) {
        if (tid < s) { sh[tid] += sh[tid + s]; sd[tid] += sd[tid + s]; }
        __syncthreads();
    }
    if (tid == 0 && out_size >= Z_ + 18) {
        out[Z_] = 1.25f * sd[0] * (1.0f / 16777216.0f);
        float kld = (float)(6.931471805599453 * 4096.0);  // log(1024) * T
        #pragma unroll
        for (int i = 0; i < 16; i++) out[Z_ + 1 + i] = kld;
        out[Z_ + 17] = expf(sh[0]);
    }
}

extern "C" void kernel_launch(void* const* d_in, const int* in_sizes, int n_in,
                              void* d_out, int out_size) {
    const float* inputs = (const float*)d_in[0];
    const float* embed  = (const float*)d_in[1];
    float* out = (float*)d_out;

    const int SMEM = 128 * LDQ + 2 * CH * LDQ + K_ * 4 + 128 * 4 + 128 * 4 + 128 * CMAX * 4; // 69632 B
    cudaFuncSetAttribute(k_main, cudaFuncAttributeMaxDynamicSharedMemorySize, SMEM);

    k_prep<<<256, 256>>>(embed);
    k_transpose<<<dim3(T_ / 32, D_ / 32, B_), dim3(32, 8)>>>(inputs);
    k_main<<<N_ / 128, 256, SMEM>>>(embed);
    k_gather<<<N_ / 32, 256>>>(embed, out, out_size);
    k_final<<<1, 1024>>>(out, out_size);
}

// round 7
// speedup vs baseline: 1.8954x; 1.8954x over previous
#include <cuda_runtime.h>
#include <cuda_bf16.h>
#include <cuda_fp16.h>
#include <cstdint>
#include <cfloat>
#include <math.h>

#define B_  16
#define D_  256
#define T_  4096
#define N_  65536                  // B_*T_
#define K_  1024
#define Z_  16777216               // N_*D_

#define CH      32                 // codewords per chunk
#define NCHUNK  (K_/CH)            // 32
#define LDB     528                // padded smem row stride in BYTES (33 x 16B, odd -> conflict-free ldmatrix)
#define CMAX    16                 // candidate list capacity per row
#define MARGIN  1.0f

// ---------------- scratch (static device memory) ----------------
__device__ __align__(16) float          g_Xf [N_ * D_];   // 64MB fp32 transposed inputs [n][d]
__device__ __align__(16) __nv_bfloat16  g_Xbf[N_ * D_];   // 32MB bf16 transposed inputs
__device__ __align__(16) __nv_bfloat16  g_Ebf[K_ * D_];   // 512KB bf16 codebook
__device__ __align__(16) float g_e2[K_];
__device__ float g_qd2[N_];
__device__ int   g_counts[K_];

// ---------------- helpers ----------------
__device__ __forceinline__ unsigned fkey(float f) {       // order-preserving float->uint
    unsigned u = __float_as_uint(f);
    return u ^ ((unsigned)((int)u >> 31) | 0x80000000u);
}
__device__ __forceinline__ float fdecode(unsigned u) {
    unsigned m = (u >> 31) ? 0x80000000u : 0xFFFFFFFFu;
    return __uint_as_float(u ^ m);
}
__device__ __forceinline__ void cp16(uint32_t dst, const void* src) {
    asm volatile("cp.async.cg.shared.global [%0], [%1], 16;" :: "r"(dst), "l"(src));
}
__device__ __forceinline__ void ldsm4(uint32_t r[4], uint32_t addr) {
    asm volatile("ldmatrix.sync.aligned.m8n8.x4.shared.b16 {%0,%1,%2,%3}, [%4];"
                 : "=r"(r[0]), "=r"(r[1]), "=r"(r[2]), "=r"(r[3]) : "r"(addr));
}
__device__ __forceinline__ void mma16816(float c[4], const uint32_t a[4],
                                         uint32_t b0, uint32_t b1) {
    asm volatile(
        "mma.sync.aligned.m16n8k16.row.col.f32.bf16.bf16.f32 "
        "{%0,%1,%2,%3}, {%4,%5,%6,%7}, {%8,%9}, {%0,%1,%2,%3};"
        : "+f"(c[0]), "+f"(c[1]), "+f"(c[2]), "+f"(c[3])
        : "r"(a[0]), "r"(a[1]), "r"(a[2]), "r"(a[3]), "r"(b0), "r"(b1));
}
// exact fp32 distance, warp-cooperative
__device__ __forceinline__ float dist2(float4 xv0, float4 xv1, const float* e, int lane) {
    const float4* er = (const float4*)e;
    float4 ev0 = er[lane * 2], ev1 = er[lane * 2 + 1];
    float d0 = xv0.x - ev0.x, d1 = xv0.y - ev0.y, d2 = xv0.z - ev0.z, d3 = xv0.w - ev0.w;
    float part = d0 * d0 + d1 * d1 + d2 * d2 + d3 * d3;
    d0 = xv1.x - ev1.x; d1 = xv1.y - ev1.y; d2 = xv1.z - ev1.z; d3 = xv1.w - ev1.w;
    part += d0 * d0 + d1 * d1 + d2 * d2 + d3 * d3;
    #pragma unroll
    for (int off = 16; off; off >>= 1) part += __shfl_xor_sync(0xffffffffu, part, off);
    return part;
}

// ---------------- prep: counts=0, bf16 codebook, e2 ----------------
__global__ void k_prep(const float* __restrict__ embed) {
    __shared__ float wsum[8];
    int tid = threadIdx.x;
    int i = blockIdx.x * 256 + tid;                  // float4 index over K_*D_/4 = 65536
    float4 v = ((const float4*)embed)[i];
    __nv_bfloat162 lo = __floats2bfloat162_rn(v.x, v.y);
    __nv_bfloat162 hi = __floats2bfloat162_rn(v.z, v.w);
    uint2 p;
    p.x = *reinterpret_cast<uint32_t*>(&lo);
    p.y = *reinterpret_cast<uint32_t*>(&hi);
    ((uint2*)g_Ebf)[i] = p;
    float s = v.x * v.x + v.y * v.y + v.z * v.z + v.w * v.w;
    #pragma unroll
    for (int off = 16; off; off >>= 1) s += __shfl_xor_sync(0xffffffffu, s, off);
    if ((tid & 31) == 0) wsum[tid >> 5] = s;
    if (blockIdx.x < 4) g_counts[blockIdx.x * 256 + tid] = 0;
    __syncthreads();
    if (tid < 4) g_e2[blockIdx.x * 4 + tid] = wsum[2 * tid] + wsum[2 * tid + 1];
}

// inputs (B, D, T) -> g_Xf fp32 [n][d] + g_Xbf bf16 [n][d]
__global__ void k_transpose(const float* __restrict__ in) {
    __shared__ float tile[32][33];
    int b = blockIdx.z, d0 = blockIdx.y * 32, t0 = blockIdx.x * 32;
    int tx = threadIdx.x, ty = threadIdx.y;
    const float* src = in + ((size_t)b * D_ + d0) * T_ + t0;
    #pragma unroll
    for (int i = 0; i < 4; i++) tile[ty + 8 * i][tx] = src[(size_t)(ty + 8 * i) * T_ + tx];
    __syncthreads();
    float* dst = g_Xf + ((size_t)b * T_ + t0) * D_ + d0;
    #pragma unroll
    for (int i = 0; i < 4; i++) dst[(size_t)(ty + 8 * i) * D_ + tx] = tile[tx][ty + 8 * i];
    if (tx < 16) {
        #pragma unroll
        for (int i = 0; i < 4; i++) {
            int t = ty + 8 * i;
            __nv_bfloat162 h = __floats2bfloat162_rn(tile[2 * tx][t], tile[2 * tx + 1][t]);
            *reinterpret_cast<uint32_t*>(g_Xbf + ((size_t)(b * T_ + t0 + t)) * D_ + d0 + 2 * tx)
                = *reinterpret_cast<uint32_t*>(&h);
        }
    }
}

// ---------------- main: persistent-A mma + online candidates + exact refine + fused gather ----------------
__global__ void __launch_bounds__(256, 2) k_main(const float* __restrict__ embed,
                                                 float* __restrict__ out, int out_size) {
    extern __shared__ char sm[];
    char* Xs = sm;                                   // 128 rows x LDB
    char* Es = sm + 128 * LDB;                       // 2 x CH x LDB
    float*    e2s     = (float*)(sm + 128 * LDB + 2 * CH * LDB);   // 1024 floats
    unsigned* rowminU = (unsigned*)(e2s + K_);                     // 128
    int*      cnt     = (int*)(rowminU + 128);                     // 128
    int*      bidx    = (int*)(cnt + 128);                         // 128
    unsigned* list    = (unsigned*)(bidx + 128);                   // 128*CMAX

    const int tid  = threadIdx.x;
    const int Nbase = blockIdx.x * 128;
    const int lane = tid & 31, w = tid >> 5;
    const int g = lane >> 2, tg = lane & 3;

    const uint32_t XsA  = (uint32_t)__cvta_generic_to_shared(Xs);
    const uint32_t EsA0 = (uint32_t)__cvta_generic_to_shared(Es);
    const uint32_t EsA1 = EsA0 + CH * LDB;

    // ---- prologue: group A = X tile + E0 ; group B = E1 ----
    {
        const __nv_bfloat16* src = g_Xbf + (size_t)Nbase * D_;
        #pragma unroll
        for (int i = 0; i < 16; i++) {
            int j = tid + i * 256, row = j >> 5, u = j & 31;
            cp16(XsA + row * LDB + u * 16, src + (size_t)row * D_ + u * 8);
        }
        const __nv_bfloat16* es = g_Ebf;
        #pragma unroll
        for (int i = 0; i < 4; i++) {
            int j = tid + i * 256, row = j >> 5, u = j & 31;
            cp16(EsA0 + row * LDB + u * 16, es + (size_t)row * D_ + u * 8);
        }
        asm volatile("cp.async.commit_group;");
        es = g_Ebf + CH * D_;
        #pragma unroll
        for (int i = 0; i < 4; i++) {
            int j = tid + i * 256, row = j >> 5, u = j & 31;
            cp16(EsA1 + row * LDB + u * 16, es + (size_t)row * D_ + u * 8);
        }
        asm volatile("cp.async.commit_group;");
    }
    // e2 table + per-row state init (overlaps cp.async)
    ((float4*)e2s)[tid] = ((const float4*)g_e2)[tid];
    if (tid < 128) { rowminU[tid] = 0xFFFFFFFFu; cnt[tid] = 0; }

    // warp w owns m-tile rows [w*16, w*16+16); A fragments persist across all chunks
    const uint32_t aAddr = XsA + (uint32_t)((w * 16 + (lane & 15)) * LDB + (lane >> 4) * 16);
    const uint32_t bOff  = (uint32_t)((lane & 15) * LDB + (lane >> 4) * 16);

    uint32_t afr[16][4];

    #pragma unroll 1
    for (int c = 0; c < NCHUNK; c++) {
        if (c == 0) { asm volatile("cp.async.wait_group 1;" ::: "memory"); }
        else        { asm volatile("cp.async.wait_group 0;" ::: "memory"); }
        __syncthreads();   // buffer (c+1)&1 free (last read in chunk c-1) + chunk c's E landed

        if (c == 0) {
            // one-time A fragment load (X tile ready)
            #pragma unroll
            for (int ks = 0; ks < 16; ks++) ldsm4(afr[ks], aAddr + ks * 32);
        } else if (c + 1 < NCHUNK) {
            // prefetch chunk c+1 into its buffer (full chunk of time to land)
            uint32_t dstA = ((c + 1) & 1) ? EsA1 : EsA0;
            const __nv_bfloat16* es = g_Ebf + (size_t)(c + 1) * CH * D_;
            #pragma unroll
            for (int i = 0; i < 4; i++) {
                int j = tid + i * 256, row = j >> 5, u = j & 31;
                cp16(dstA + row * LDB + u * 16, es + (size_t)row * D_ + u * 8);
            }
            asm volatile("cp.async.commit_group;");
        }

        const uint32_t bAddr = ((c & 1) ? EsA1 : EsA0) + bOff;

        float acc[4][4];
        #pragma unroll
        for (int tn = 0; tn < 4; tn++)
            #pragma unroll
            for (int q = 0; q < 4; q++) acc[tn][q] = 0.f;

        #pragma unroll
        for (int ks = 0; ks < 16; ks++) {
            uint32_t b0[4], b1[4];
            ldsm4(b0, bAddr + ks * 32);               // codewords 0..15 of chunk
            ldsm4(b1, bAddr + 16 * LDB + ks * 32);    // codewords 16..31
            mma16816(acc[0], afr[ks], b0[0], b0[2]);
            mma16816(acc[1], afr[ks], b0[1], b0[3]);
            mma16816(acc[2], afr[ks], b1[0], b1[2]);
            mma16816(acc[3], afr[ks], b1[1], b1[3]);
        }

        // scores + running row-min (rows: w*16 + (q>>1)*8 + g)
        float lmin[2] = {FLT_MAX, FLT_MAX};
        #pragma unroll
        for (int tn = 0; tn < 4; tn++) {
            int kc = c * CH + tn * 8 + tg * 2;
            float e20 = e2s[kc], e21 = e2s[kc + 1];
            acc[tn][0] = fmaf(-2.f, acc[tn][0], e20);
            acc[tn][1] = fmaf(-2.f, acc[tn][1], e21);
            acc[tn][2] = fmaf(-2.f, acc[tn][2], e20);
            acc[tn][3] = fmaf(-2.f, acc[tn][3], e21);
            lmin[0] = fminf(lmin[0], fminf(acc[tn][0], acc[tn][1]));
            lmin[1] = fminf(lmin[1], fminf(acc[tn][2], acc[tn][3]));
        }
        #pragma unroll
        for (int s = 0; s < 2; s++) {
            float v = lmin[s];
            v = fminf(v, __shfl_xor_sync(0xffffffffu, v, 1));
            v = fminf(v, __shfl_xor_sync(0xffffffffu, v, 2));
            if (tg == 0) atomicMin(&rowminU[w * 16 + s * 8 + g], fkey(v));
        }
        // chunk 0 needs a converged min; stale mins are provably safe afterwards
        if (c == 0) __syncthreads();

        // candidate collection vs current (possibly stale) row minima + MARGIN
        float thr[2];
        thr[0] = fdecode(rowminU[w * 16 + g]) + MARGIN;
        thr[1] = fdecode(rowminU[w * 16 + 8 + g]) + MARGIN;
        #pragma unroll
        for (int tn = 0; tn < 4; tn++)
            #pragma unroll
            for (int q = 0; q < 4; q++) {
                float sc = acc[tn][q];
                if (sc <= thr[q >> 1]) {
                    int row = w * 16 + (q >> 1) * 8 + g;
                    int kk  = c * CH + tn * 8 + tg * 2 + (q & 1);
                    int pos = atomicAdd(&cnt[row], 1);
                    if (pos < CMAX)
                        list[row * CMAX + pos] =
                            ((unsigned)kk << 16) |
                            (unsigned)__half_as_ushort(__float2half_rn(sc));
                }
            }
    }
    __syncthreads();

    // ---- exact refine: warp w owns rows [w*16, w*16+16) ----
    for (int rr = 0; rr < 16; rr++) {
        int row = w * 16 + rr;
        size_t n = (size_t)Nbase + row;
        float rmn = fdecode(rowminU[row]);
        int c_ = cnt[row];
        const float4* xr = (const float4*)(g_Xf + n * D_);
        float4 xv0 = xr[lane * 2], xv1 = xr[lane * 2 + 1];
        float bestd = FLT_MAX; int bestk = 0;
        if (c_ <= CMAX) {
            float thr = rmn + MARGIN + 0.5f;   // + half-precision storage slack
            unsigned e = (lane < c_) ? list[row * CMAX + lane] : 0u;
            float sh = (lane < c_)
                ? __half2float(__ushort_as_half((unsigned short)(e & 0xFFFFu))) : FLT_MAX;
            unsigned mk = __ballot_sync(0xffffffffu, sh <= thr);
            while (mk) {
                int j = __ffs(mk) - 1; mk &= mk - 1;
                int kc = (int)(__shfl_sync(0xffffffffu, e, j) >> 16);
                float part = dist2(xv0, xv1, embed + (size_t)kc * D_, lane);
                if (part < bestd || (part == bestd && kc < bestk)) { bestd = part; bestk = kc; }
            }
        } else {
            // overflow fallback (statistically ~never): exact scan of all codewords
            for (int kc = 0; kc < K_; kc++) {
                float part = dist2(xv0, xv1, embed + (size_t)kc * D_, lane);
                if (part < bestd) { bestd = part; bestk = kc; }
            }
        }
        if (lane == 0) {
            bidx[row] = bestk;
            g_qd2[n]  = bestd;
            atomicAdd(&g_counts[bestk], 1);
        }
    }
    __syncthreads();

    // ---- fused gather: CTA rows are 128 consecutive t within one b ----
    // warp w owns d-slice [w*32, w*32+32); lane = t within each 32-t group
    if (out_size >= Z_) {
        int b  = Nbase >> 12;
        int tb = Nbase & (T_ - 1);
        #pragma unroll
        for (int grp = 0; grp < 4; grp++) {
            int row = grp * 32 + lane;
            int kt = bidx[row];
            const float4* er = (const float4*)(embed + (size_t)kt * D_) + w * 8;
            float* ob = out + (size_t)b * D_ * T_ + (size_t)(w * 32) * T_ + tb + row;
            #pragma unroll
            for (int q = 0; q < 8; q++) {
                float4 v = er[q];
                ob[(size_t)(q * 4) * T_]     = v.x;
                ob[(size_t)(q * 4 + 1) * T_] = v.y;
                ob[(size_t)(q * 4 + 2) * T_] = v.z;
                ob[(size_t)(q * 4 + 3) * T_] = v.w;
            }
        }
    }
}

// ---------------- scalars: loss, kldiv (constant), perplexity ----------------
__global__ void k_final(float* __restrict__ out, int out_size) {
    __shared__ float sh[1024], sd[1024];
    int tid = threadIdx.x;
    float p = (float)g_counts[tid] * (1.0f / 65536.0f);
    sh[tid] = -p * logf(p + 1e-10f);
    float ds = 0.f;
    #pragma unroll 8
    for (int i = 0; i < 64; i++) ds += g_qd2[tid + i * 1024];
    sd[tid] = ds;
    __syncthreads();
    for (int s = 512; s; s >>= 1) {
        if (tid < s) { sh[tid] += sh[tid + s]; sd[tid] += sd[tid + s]; }
        __syncthreads();
    }
    if (tid == 0 && out_size >= Z_ + 18) {
        out[Z_] = 1.25f * sd[0] * (1.0f / 16777216.0f);
        float kld = (float)(6.931471805599453 * 4096.0);  // log(1024) * T
        #pragma unroll
        for (int i = 0; i < 16; i++) out[Z_ + 1 + i] = kld;
        out[Z_ + 17] = expf(sh[0]);
    }
}

extern "C" void kernel_launch(void* const* d_in, const int* in_sizes, int n_in,
                              void* d_out, int out_size) {
    const float* inputs = (const float*)d_in[0];
    const float* embed  = (const float*)d_in[1];
    float* out = (float*)d_out;

    const int SMEM = 128 * LDB + 2 * CH * LDB + K_ * 4 + 128 * 4 + 128 * 4 + 128 * 4
                   + 128 * CMAX * 4;   // 115200 B -> 2 CTAs/SM (230400 <= 233472)
    cudaFuncSetAttribute(k_main, cudaFuncAttributeMaxDynamicSharedMemorySize, SMEM);

    k_prep<<<256, 256>>>(embed);
    k_transpose<<<dim3(T_ / 32, D_ / 32, B_), dim3(32, 8)>>>(inputs);
    k_main<<<N_ / 128, 256, SMEM>>>(embed, out, out_size);
    k_final<<<1, 1024>>>(out, out_size);
}